// round 12
// baseline (speedup 1.0000x reference)
#include <cuda_runtime.h>
#include <cuda_fp16.h>
#include <cstdint>

#define N_NODES 50000
#define N_EDGES 800000
#define F 64
#define C 16
#define N_TILES ((N_NODES + 63) / 64)              // 782
#define XH_WORDS (N_NODES * F / 2)                 // 1.6M half2 words

// ---------------- device scratch (device-code references ONLY) ----------
__device__ __align__(256) float  g_agg1[N_NODES * F];   // mean_agg(x), fp32
__device__ __align__(256) __half g_xh  [N_NODES * F];   // x as fp16
__device__ __align__(256) __half g_p2h [N_NODES * C];   // h1 @ Wn2, fp16
__device__ __align__(256) float  g_q2  [N_NODES * C];   // h1 @ Ws2, fp32
__device__ int g_csr_src[N_EDGES];
__device__ int g_cnt[N_NODES];                          // zeroed at end of each run
__device__ int g_off[N_NODES + 1];
__device__ int g_cursor[N_NODES];

// ---------------- packed f32x2 helpers ----------------
__device__ __forceinline__ unsigned long long pack2(float a, float b) {
    unsigned long long r;
    asm("mov.b64 %0, {%1, %2};" : "=l"(r) : "f"(a), "f"(b));
    return r;
}
__device__ __forceinline__ unsigned long long fma2(unsigned long long a,
                                                   unsigned long long b,
                                                   unsigned long long c) {
    unsigned long long d;
    asm("fma.rn.f32x2 %0, %1, %2, %3;" : "=l"(d) : "l"(a), "l"(b), "l"(c));
    return d;
}
__device__ __forceinline__ void unpack2(unsigned long long v, float& lo, float& hi) {
    asm("mov.b64 {%0, %1}, %2;" : "=f"(lo), "=f"(hi) : "l"(v));
}

// ---------------- inline int64-vs-int32 layout detection -----------------
// Indices in [0, 50000): little-endian int64 => all odd 32-bit words zero.
// P(false int64 with random int32 data) = (1/50000)^8 ~ 0. Uniform branch.
__device__ __forceinline__ bool detect_is64(const unsigned int* __restrict__ raw) {
    unsigned int o = raw[1] | raw[3] | raw[5] | raw[7]
                   | raw[9] | raw[11] | raw[13] | raw[15];
    return o == 0u;
}

// ---------------- hist (dst histogram) + x -> fp16 conversion ------------
// grid = 6250 x 256 = 1.6M threads (= XH_WORDS exactly; first 800k do hist).
__global__ void hist_convert_kernel(const int* __restrict__ raw_dst,
                                    const float* __restrict__ x) {
    int gid = blockIdx.x * blockDim.x + threadIdx.x;
    bool is64 = detect_is64((const unsigned int*)raw_dst);
    if (gid < N_EDGES) {
        int d = raw_dst[is64 ? 2 * gid : gid];
        atomicAdd(&g_cnt[d], 1);
    }
    if (gid < XH_WORDS) {
        float2 v = *(const float2*)(x + 2 * (size_t)gid);
        *(__half2*)(g_xh + 2 * (size_t)gid) = __floats2half2_rn(v.x, v.y);
    }
}

// ---------------- single-launch exclusive scan: g_cnt -> g_off/cursor ----
#define SCAN_PER 49
__global__ void scan_fused_kernel() {
    __shared__ int sh[1024];
    int t = threadIdx.x;
    int base = t * SCAN_PER;
    int sum = 0;
#pragma unroll 7
    for (int i = 0; i < SCAN_PER; i++) {
        int idx = base + i;
        if (idx < N_NODES) sum += g_cnt[idx];
    }
    sh[t] = sum;
    __syncthreads();
#pragma unroll
    for (int d = 1; d < 1024; d <<= 1) {
        int a = (t >= d) ? sh[t - d] : 0;
        __syncthreads();
        sh[t] += a;
        __syncthreads();
    }
    int run = sh[t] - sum;
#pragma unroll 7
    for (int i = 0; i < SCAN_PER; i++) {
        int idx = base + i;
        if (idx < N_NODES) {
            int c = g_cnt[idx];
            g_off[idx] = run;
            g_cursor[idx] = run;
            run += c;
        }
    }
    if (t == 0) g_off[N_NODES] = N_EDGES;
}

// ---------------- fill CSR (reads raw indices directly) ------------------
__global__ void fill_kernel(const int* __restrict__ raw_src,
                            const int* __restrict__ raw_dst) {
    int e = blockIdx.x * blockDim.x + threadIdx.x;
    if (e >= N_EDGES) return;
    bool is64 = detect_is64((const unsigned int*)raw_src);
    int idx = is64 ? 2 * e : e;
    int s = raw_src[idx];
    int d = raw_dst[idx];
    int pos = atomicAdd(&g_cursor[d], 1);
    g_csr_src[pos] = s;
}

// ---------------- gather1: agg1[n] = mean of xh[neighbors], fp16 loads ---
// 16 lanes/node (64 halfs = 16 x uint2), 256 thr = 16 nodes/block.
// unroll-8 of 8B loads: MLP=8 at R4-level register pressure.
// Also re-zeroes g_cnt for the next graph replay (scan already consumed it).
__global__ void gather1_kernel() {
    int gid = blockIdx.x * blockDim.x + threadIdx.x;
    if (gid < N_NODES) g_cnt[gid] = 0;     // prep next replay

    int node = blockIdx.x * 16 + (threadIdx.x >> 4);
    int l = threadIdx.x & 15;
    if (node >= N_NODES) return;
    int beg = g_off[node], end = g_off[node + 1];
    float4 acc = make_float4(0.f, 0.f, 0.f, 0.f);
    int i = beg;
    for (; i + 8 <= end; i += 8) {
        uint2 w0 = *(const uint2*)(g_xh + (size_t)g_csr_src[i]     * F + l * 4);
        uint2 w1 = *(const uint2*)(g_xh + (size_t)g_csr_src[i + 1] * F + l * 4);
        uint2 w2 = *(const uint2*)(g_xh + (size_t)g_csr_src[i + 2] * F + l * 4);
        uint2 w3 = *(const uint2*)(g_xh + (size_t)g_csr_src[i + 3] * F + l * 4);
        uint2 w4 = *(const uint2*)(g_xh + (size_t)g_csr_src[i + 4] * F + l * 4);
        uint2 w5 = *(const uint2*)(g_xh + (size_t)g_csr_src[i + 5] * F + l * 4);
        uint2 w6 = *(const uint2*)(g_xh + (size_t)g_csr_src[i + 6] * F + l * 4);
        uint2 w7 = *(const uint2*)(g_xh + (size_t)g_csr_src[i + 7] * F + l * 4);
#pragma unroll
        for (int u = 0; u < 8; u++) {
            uint2 w = (u == 0) ? w0 : (u == 1) ? w1 : (u == 2) ? w2 : (u == 3) ? w3
                    : (u == 4) ? w4 : (u == 5) ? w5 : (u == 6) ? w6 : w7;
            float2 f0 = __half22float2(*(__half2*)&w.x);
            float2 f1 = __half22float2(*(__half2*)&w.y);
            acc.x += f0.x; acc.y += f0.y; acc.z += f1.x; acc.w += f1.y;
        }
    }
    for (; i < end; i++) {
        uint2 w = *(const uint2*)(g_xh + (size_t)g_csr_src[i] * F + l * 4);
        float2 f0 = __half22float2(*(__half2*)&w.x);
        float2 f1 = __half22float2(*(__half2*)&w.y);
        acc.x += f0.x; acc.y += f0.y; acc.z += f1.x; acc.w += f1.y;
    }
    float inv = 1.0f / (float)max(end - beg, 1);
    acc.x *= inv; acc.y *= inv; acc.z *= inv; acc.w *= inv;
    *(float4*)(g_agg1 + (size_t)node * F + l * 4) = acc;
}

// ---------------- layer1 (persistent, f32x2, dynamic smem) --------------
// h = relu(x@Ws1 + agg1@Wn1 + b1);  p2h = fp16(h@Wn2);  q2 = h@Ws2.
#define SM_W   0
#define SM_W2  (128 * 64)
#define SM_XP  (SM_W2 + 64 * 32)
#define SM_AP  (SM_XP + 16 * 68)
#define SM_H   (SM_AP + 16 * 68)
#define SM_TOT (SM_H + 64 * 68)          // 16768 floats = 67072 B

__global__ void __launch_bounds__(256, 2)
layer1_kernel(const float* __restrict__ x,
              const float* __restrict__ Ws1,
              const float* __restrict__ Wn1,
              const float* __restrict__ b1,
              const float* __restrict__ Wn2,
              const float* __restrict__ Ws2) {
    extern __shared__ float sm[];
    int tid = threadIdx.x;

    for (int i = tid; i < 64 * 64; i += 256) {
        int k = i >> 6, c = i & 63;
        sm[SM_W + k * 64 + c]        = Ws1[i];
        sm[SM_W + (64 + k) * 64 + c] = Wn1[i];
    }
    for (int i = tid; i < 64 * 16; i += 256) {
        int k = i >> 4, c = i & 15;
        sm[SM_W2 + k * 32 + c]      = Wn2[i];
        sm[SM_W2 + k * 32 + 16 + c] = Ws2[i];
    }
    __syncthreads();

    int ty = tid >> 4, tx = tid & 15;
    float4 bb = *(const float4*)(b1 + tx * 4);

    for (int tile = blockIdx.x; tile < N_TILES; tile += gridDim.x) {
        int node0 = tile * 64;
        unsigned long long acc[4][2];
#pragma unroll
        for (int i = 0; i < 4; i++) { acc[i][0] = 0ull; acc[i][1] = 0ull; }

#pragma unroll
        for (int kp = 0; kp < 4; kp++) {
            __syncthreads();
            {   // k-panel: 64 nodes x 16 k, transposed into [k][node]
                int n = tid >> 2, ch = tid & 3;
                int node = node0 + n;
                float4 vx = make_float4(0.f, 0.f, 0.f, 0.f);
                float4 va = make_float4(0.f, 0.f, 0.f, 0.f);
                if (node < N_NODES) {
                    vx = *(const float4*)(x      + (size_t)node * F + kp * 16 + ch * 4);
                    va = *(const float4*)(g_agg1 + (size_t)node * F + kp * 16 + ch * 4);
                }
                int kb = ch * 4;
                sm[SM_XP + (kb + 0) * 68 + n] = vx.x;
                sm[SM_XP + (kb + 1) * 68 + n] = vx.y;
                sm[SM_XP + (kb + 2) * 68 + n] = vx.z;
                sm[SM_XP + (kb + 3) * 68 + n] = vx.w;
                sm[SM_AP + (kb + 0) * 68 + n] = va.x;
                sm[SM_AP + (kb + 1) * 68 + n] = va.y;
                sm[SM_AP + (kb + 2) * 68 + n] = va.z;
                sm[SM_AP + (kb + 3) * 68 + n] = va.w;
            }
            __syncthreads();
#pragma unroll
            for (int k = 0; k < 16; k++) {
                float4 xv = *(float4*)&sm[SM_XP + k * 68 + ty * 4];
                float4 av = *(float4*)&sm[SM_AP + k * 68 + ty * 4];
                unsigned long long wsp0, wsp1, wnp0, wnp1;
                {
                    float4 ws = *(float4*)&sm[SM_W + (kp * 16 + k) * 64 + tx * 4];
                    float4 wn = *(float4*)&sm[SM_W + (64 + kp * 16 + k) * 64 + tx * 4];
                    wsp0 = pack2(ws.x, ws.y); wsp1 = pack2(ws.z, ws.w);
                    wnp0 = pack2(wn.x, wn.y); wnp1 = pack2(wn.z, wn.w);
                }
                unsigned long long xs[4], as_[4];
                xs[0] = pack2(xv.x, xv.x); xs[1] = pack2(xv.y, xv.y);
                xs[2] = pack2(xv.z, xv.z); xs[3] = pack2(xv.w, xv.w);
                as_[0] = pack2(av.x, av.x); as_[1] = pack2(av.y, av.y);
                as_[2] = pack2(av.z, av.z); as_[3] = pack2(av.w, av.w);
#pragma unroll
                for (int i = 0; i < 4; i++) {
                    acc[i][0] = fma2(wsp0, xs[i], acc[i][0]);
                    acc[i][0] = fma2(wnp0, as_[i], acc[i][0]);
                    acc[i][1] = fma2(wsp1, xs[i], acc[i][1]);
                    acc[i][1] = fma2(wnp1, as_[i], acc[i][1]);
                }
            }
        }
        // relu + bias -> sH
#pragma unroll
        for (int i = 0; i < 4; i++) {
            float h0, h1, h2, h3;
            unpack2(acc[i][0], h0, h1);
            unpack2(acc[i][1], h2, h3);
            float4 hv;
            hv.x = fmaxf(h0 + bb.x, 0.f);
            hv.y = fmaxf(h1 + bb.y, 0.f);
            hv.z = fmaxf(h2 + bb.z, 0.f);
            hv.w = fmaxf(h3 + bb.w, 0.f);
            *(float4*)&sm[SM_H + (ty * 4 + i) * 68 + tx * 4] = hv;
        }
        __syncthreads();
        // epilogue: p2h = fp16(h@Wn2); q2 = h@Ws2.
        {
            int n = tid >> 2, part = tid & 3;
            unsigned long long o[4] = {0ull, 0ull, 0ull, 0ull};
#pragma unroll 8
            for (int k = 0; k < 64; k++) {
                float hv = sm[SM_H + n * 68 + k];
                unsigned long long hs = pack2(hv, hv);
                float4 w0 = *(float4*)&sm[SM_W2 + k * 32 + part * 8];
                float4 w1 = *(float4*)&sm[SM_W2 + k * 32 + part * 8 + 4];
                o[0] = fma2(pack2(w0.x, w0.y), hs, o[0]);
                o[1] = fma2(pack2(w0.z, w0.w), hs, o[1]);
                o[2] = fma2(pack2(w1.x, w1.y), hs, o[2]);
                o[3] = fma2(pack2(w1.z, w1.w), hs, o[3]);
            }
            int node = node0 + n;
            if (node < N_NODES) {
                float f0, f1, f2, f3, f4, f5, f6, f7;
                unpack2(o[0], f0, f1); unpack2(o[1], f2, f3);
                unpack2(o[2], f4, f5); unpack2(o[3], f6, f7);
                if (part < 2) {
                    __half2 ha = __floats2half2_rn(f0, f1);
                    __half2 hb = __floats2half2_rn(f2, f3);
                    __half2 hc = __floats2half2_rn(f4, f5);
                    __half2 hd = __floats2half2_rn(f6, f7);
                    uint4 w;
                    w.x = *(unsigned int*)&ha;
                    w.y = *(unsigned int*)&hb;
                    w.z = *(unsigned int*)&hc;
                    w.w = *(unsigned int*)&hd;
                    *(uint4*)(g_p2h + (size_t)node * C + part * 8) = w;
                } else {
                    float4 r0 = make_float4(f0, f1, f2, f3);
                    float4 r1 = make_float4(f4, f5, f6, f7);
                    *(float4*)(g_q2 + (size_t)node * C + (part - 2) * 8)     = r0;
                    *(float4*)(g_q2 + (size_t)node * C + (part - 2) * 8 + 4) = r1;
                }
            }
        }
        __syncthreads();
    }
}

// ---------------- gather2 + output: out = q2 + mean_agg(p2h) + b2 -------
// 4 lanes/node (16 halfs = 4 x uint2), 256 thr = 64 nodes/block.
__global__ void gather2_out_kernel(const float* __restrict__ b2,
                                   float* __restrict__ out) {
    int node = blockIdx.x * 64 + (threadIdx.x >> 2);
    int l = threadIdx.x & 3;
    if (node >= N_NODES) return;
    int beg = g_off[node], end = g_off[node + 1];
    float4 acc = make_float4(0.f, 0.f, 0.f, 0.f);
    int i = beg;
    for (; i + 4 <= end; i += 4) {
        uint2 w0 = *(const uint2*)(g_p2h + (size_t)g_csr_src[i]     * C + l * 4);
        uint2 w1 = *(const uint2*)(g_p2h + (size_t)g_csr_src[i + 1] * C + l * 4);
        uint2 w2 = *(const uint2*)(g_p2h + (size_t)g_csr_src[i + 2] * C + l * 4);
        uint2 w3 = *(const uint2*)(g_p2h + (size_t)g_csr_src[i + 3] * C + l * 4);
#pragma unroll
        for (int u = 0; u < 4; u++) {
            uint2 w = (u == 0) ? w0 : (u == 1) ? w1 : (u == 2) ? w2 : w3;
            float2 f0 = __half22float2(*(__half2*)&w.x);
            float2 f1 = __half22float2(*(__half2*)&w.y);
            acc.x += f0.x; acc.y += f0.y; acc.z += f1.x; acc.w += f1.y;
        }
    }
    for (; i < end; i++) {
        uint2 w = *(const uint2*)(g_p2h + (size_t)g_csr_src[i] * C + l * 4);
        float2 f0 = __half22float2(*(__half2*)&w.x);
        float2 f1 = __half22float2(*(__half2*)&w.y);
        acc.x += f0.x; acc.y += f0.y; acc.z += f1.x; acc.w += f1.y;
    }
    float inv = 1.0f / (float)max(end - beg, 1);
    float4 q = *(const float4*)(g_q2 + (size_t)node * C + l * 4);
    float4 bv = *(const float4*)(b2 + l * 4);
    float4 r;
    r.x = q.x + acc.x * inv + bv.x;
    r.y = q.y + acc.y * inv + bv.y;
    r.z = q.z + acc.z * inv + bv.z;
    r.w = q.w + acc.w * inv + bv.w;
    *(float4*)(out + (size_t)node * C + l * 4) = r;
}

// ---------------- launch ----------------
extern "C" void kernel_launch(void* const* d_in, const int* in_sizes, int n_in,
                              void* d_out, int out_size) {
    const float* x   = (const float*)d_in[0];
    const int*   src = (const int*)d_in[1];
    const int*   dst = (const int*)d_in[2];
    const float* Ws1 = (const float*)d_in[3];
    const float* Wn1 = (const float*)d_in[4];
    const float* b1  = (const float*)d_in[5];
    const float* Ws2 = (const float*)d_in[6];
    const float* Wn2 = (const float*)d_in[7];
    const float* b2  = (const float*)d_in[8];
    float* out = (float*)d_out;

    // host-side attribute set; runs at capture time, not during replay
    cudaFuncSetAttribute(layer1_kernel,
                         cudaFuncAttributeMaxDynamicSharedMemorySize,
                         SM_TOT * (int)sizeof(float));

    hist_convert_kernel<<<(XH_WORDS + 255) / 256, 256>>>(dst, x);
    scan_fused_kernel<<<1, 1024>>>();
    fill_kernel<<<(N_EDGES + 255) / 256, 256>>>(src, dst);
    gather1_kernel<<<(N_NODES + 15) / 16, 256>>>();
    layer1_kernel<<<296, 256, SM_TOT * (int)sizeof(float)>>>(x, Ws1, Wn1, b1, Wn2, Ws2);
    gather2_out_kernel<<<(N_NODES + 63) / 64, 256>>>(b2, out);
}

// round 13
// speedup vs baseline: 1.5239x; 1.5239x over previous
#include <cuda_runtime.h>
#include <cuda_fp16.h>
#include <cstdint>

#define N_NODES 50000
#define N_EDGES 800000
#define F 64
#define C 16
#define N_TILES ((N_NODES + 63) / 64)              // 782

// ---------------- device scratch (device-code references ONLY) ----------
__device__ __align__(256) float  g_agg1[N_NODES * F];   // mean_agg(x), fp32
__device__ __align__(256) __half g_xh  [N_NODES * F];   // x as fp16
__device__ __align__(256) __half g_p2h [N_NODES * C];   // h1 @ Wn2, fp16
__device__ __align__(256) float  g_q2  [N_NODES * C];   // h1 @ Ws2, fp32
__device__ int g_src32[N_EDGES];
__device__ int g_dst32[N_EDGES];
__device__ int g_csr_src[N_EDGES];
__device__ int g_cnt[N_NODES];
__device__ int g_off[N_NODES + 1];
__device__ int g_cursor[N_NODES];
__device__ int g_is64;

// ---------------- packed f32x2 helpers ----------------
__device__ __forceinline__ unsigned long long pack2(float a, float b) {
    unsigned long long r;
    asm("mov.b64 %0, {%1, %2};" : "=l"(r) : "f"(a), "f"(b));
    return r;
}
__device__ __forceinline__ unsigned long long fma2(unsigned long long a,
                                                   unsigned long long b,
                                                   unsigned long long c) {
    unsigned long long d;
    asm("fma.rn.f32x2 %0, %1, %2, %3;" : "=l"(d) : "l"(a), "l"(b), "l"(c));
    return d;
}
__device__ __forceinline__ void unpack2(unsigned long long v, float& lo, float& hi) {
    asm("mov.b64 {%0, %1}, %2;" : "=f"(lo), "=f"(hi) : "l"(v));
}

// ---------------- detect int64-vs-int32 layout + zero counts -------------
__global__ void detect_zero_kernel(const unsigned int* __restrict__ raw_src) {
    int i = blockIdx.x * blockDim.x + threadIdx.x;
    if (i < N_NODES) g_cnt[i] = 0;
    if (blockIdx.x == 0) {
        __shared__ int any_nonzero;
        if (threadIdx.x == 0) any_nonzero = 0;
        __syncthreads();
        for (int j = threadIdx.x; j < 1024; j += blockDim.x)
            if (raw_src[2 * j + 1] != 0u) any_nonzero = 1;
        __syncthreads();
        if (threadIdx.x == 0) g_is64 = (any_nonzero == 0) ? 1 : 0;
    }
}

// ---------------- convert indices + histogram + x -> fp16 ----------------
// 800k threads: thread e stages edge e's indices + histograms dst, AND
// converts float4 x[4e..4e+3] -> uint2 of half (800k * 4 = 3.2M = N*F).
__global__ void convert_hist_kernel(const int* __restrict__ raw_src,
                                    const int* __restrict__ raw_dst,
                                    const float* __restrict__ x) {
    int e = blockIdx.x * blockDim.x + threadIdx.x;
    if (e >= N_EDGES) return;
    int idx = g_is64 ? (2 * e) : e;
    int s = raw_src[idx];
    int d = raw_dst[idx];
    g_src32[e] = s;
    g_dst32[e] = d;
    atomicAdd(&g_cnt[d], 1);
    // x conversion: 4 floats per thread
    float4 v = *(const float4*)(x + 4 * (size_t)e);
    __half2 h0 = __floats2half2_rn(v.x, v.y);
    __half2 h1 = __floats2half2_rn(v.z, v.w);
    uint2 w;
    w.x = *(unsigned int*)&h0;
    w.y = *(unsigned int*)&h1;
    *(uint2*)(g_xh + 4 * (size_t)e) = w;
}

// ---------------- single-launch exclusive scan: g_cnt -> g_off/cursor ----
#define SCAN_PER 49
__global__ void scan_fused_kernel() {
    __shared__ int sh[1024];
    int t = threadIdx.x;
    int base = t * SCAN_PER;
    int sum = 0;
#pragma unroll 7
    for (int i = 0; i < SCAN_PER; i++) {
        int idx = base + i;
        if (idx < N_NODES) sum += g_cnt[idx];
    }
    sh[t] = sum;
    __syncthreads();
#pragma unroll
    for (int d = 1; d < 1024; d <<= 1) {
        int a = (t >= d) ? sh[t - d] : 0;
        __syncthreads();
        sh[t] += a;
        __syncthreads();
    }
    int run = sh[t] - sum;
#pragma unroll 7
    for (int i = 0; i < SCAN_PER; i++) {
        int idx = base + i;
        if (idx < N_NODES) {
            int c = g_cnt[idx];
            g_off[idx] = run;
            g_cursor[idx] = run;
            run += c;
        }
    }
    if (t == 0) g_off[N_NODES] = N_EDGES;
}

// ---------------- fill CSR (L2-hot staged int32 indices) -----------------
__global__ void fill_kernel() {
    int e = blockIdx.x * blockDim.x + threadIdx.x;
    if (e >= N_EDGES) return;
    int d = g_dst32[e];
    int pos = atomicAdd(&g_cursor[d], 1);
    g_csr_src[pos] = g_src32[e];
}

// ---------------- gather1: agg1[n] = mean of xh[neighbors], fp16 loads ---
// (R12-verified: 23.5us, issue-bound.) 16 lanes/node, 256 thr = 16 nodes.
__global__ void gather1_kernel() {
    int node = blockIdx.x * 16 + (threadIdx.x >> 4);
    int l = threadIdx.x & 15;
    if (node >= N_NODES) return;
    int beg = g_off[node], end = g_off[node + 1];
    float4 acc = make_float4(0.f, 0.f, 0.f, 0.f);
    int i = beg;
    for (; i + 8 <= end; i += 8) {
        uint2 w0 = *(const uint2*)(g_xh + (size_t)g_csr_src[i]     * F + l * 4);
        uint2 w1 = *(const uint2*)(g_xh + (size_t)g_csr_src[i + 1] * F + l * 4);
        uint2 w2 = *(const uint2*)(g_xh + (size_t)g_csr_src[i + 2] * F + l * 4);
        uint2 w3 = *(const uint2*)(g_xh + (size_t)g_csr_src[i + 3] * F + l * 4);
        uint2 w4 = *(const uint2*)(g_xh + (size_t)g_csr_src[i + 4] * F + l * 4);
        uint2 w5 = *(const uint2*)(g_xh + (size_t)g_csr_src[i + 5] * F + l * 4);
        uint2 w6 = *(const uint2*)(g_xh + (size_t)g_csr_src[i + 6] * F + l * 4);
        uint2 w7 = *(const uint2*)(g_xh + (size_t)g_csr_src[i + 7] * F + l * 4);
#pragma unroll
        for (int u = 0; u < 8; u++) {
            uint2 w = (u == 0) ? w0 : (u == 1) ? w1 : (u == 2) ? w2 : (u == 3) ? w3
                    : (u == 4) ? w4 : (u == 5) ? w5 : (u == 6) ? w6 : w7;
            float2 f0 = __half22float2(*(__half2*)&w.x);
            float2 f1 = __half22float2(*(__half2*)&w.y);
            acc.x += f0.x; acc.y += f0.y; acc.z += f1.x; acc.w += f1.y;
        }
    }
    for (; i < end; i++) {
        uint2 w = *(const uint2*)(g_xh + (size_t)g_csr_src[i] * F + l * 4);
        float2 f0 = __half22float2(*(__half2*)&w.x);
        float2 f1 = __half22float2(*(__half2*)&w.y);
        acc.x += f0.x; acc.y += f0.y; acc.z += f1.x; acc.w += f1.y;
    }
    float inv = 1.0f / (float)max(end - beg, 1);
    acc.x *= inv; acc.y *= inv; acc.z *= inv; acc.w *= inv;
    *(float4*)(g_agg1 + (size_t)node * F + l * 4) = acc;
}

// ---------------- layer1 (persistent, f32x2, dynamic smem) --------------
// h = relu(x@Ws1 + agg1@Wn1 + b1);  p2h = fp16(h@Wn2);  q2 = h@Ws2.
#define SM_W   0
#define SM_W2  (128 * 64)
#define SM_XP  (SM_W2 + 64 * 32)
#define SM_AP  (SM_XP + 16 * 68)
#define SM_H   (SM_AP + 16 * 68)
#define SM_TOT (SM_H + 64 * 68)          // 16768 floats = 67072 B

__global__ void __launch_bounds__(256, 2)
layer1_kernel(const float* __restrict__ x,
              const float* __restrict__ Ws1,
              const float* __restrict__ Wn1,
              const float* __restrict__ b1,
              const float* __restrict__ Wn2,
              const float* __restrict__ Ws2) {
    extern __shared__ float sm[];
    int tid = threadIdx.x;

    for (int i = tid; i < 64 * 64; i += 256) {
        int k = i >> 6, c = i & 63;
        sm[SM_W + k * 64 + c]        = Ws1[i];
        sm[SM_W + (64 + k) * 64 + c] = Wn1[i];
    }
    for (int i = tid; i < 64 * 16; i += 256) {
        int k = i >> 4, c = i & 15;
        sm[SM_W2 + k * 32 + c]      = Wn2[i];
        sm[SM_W2 + k * 32 + 16 + c] = Ws2[i];
    }
    __syncthreads();

    int ty = tid >> 4, tx = tid & 15;
    float4 bb = *(const float4*)(b1 + tx * 4);

    for (int tile = blockIdx.x; tile < N_TILES; tile += gridDim.x) {
        int node0 = tile * 64;
        unsigned long long acc[4][2];
#pragma unroll
        for (int i = 0; i < 4; i++) { acc[i][0] = 0ull; acc[i][1] = 0ull; }

#pragma unroll
        for (int kp = 0; kp < 4; kp++) {
            __syncthreads();
            {   // k-panel: 64 nodes x 16 k, transposed into [k][node]
                int n = tid >> 2, ch = tid & 3;
                int node = node0 + n;
                float4 vx = make_float4(0.f, 0.f, 0.f, 0.f);
                float4 va = make_float4(0.f, 0.f, 0.f, 0.f);
                if (node < N_NODES) {
                    vx = *(const float4*)(x      + (size_t)node * F + kp * 16 + ch * 4);
                    va = *(const float4*)(g_agg1 + (size_t)node * F + kp * 16 + ch * 4);
                }
                int kb = ch * 4;
                sm[SM_XP + (kb + 0) * 68 + n] = vx.x;
                sm[SM_XP + (kb + 1) * 68 + n] = vx.y;
                sm[SM_XP + (kb + 2) * 68 + n] = vx.z;
                sm[SM_XP + (kb + 3) * 68 + n] = vx.w;
                sm[SM_AP + (kb + 0) * 68 + n] = va.x;
                sm[SM_AP + (kb + 1) * 68 + n] = va.y;
                sm[SM_AP + (kb + 2) * 68 + n] = va.z;
                sm[SM_AP + (kb + 3) * 68 + n] = va.w;
            }
            __syncthreads();
#pragma unroll
            for (int k = 0; k < 16; k++) {
                float4 xv = *(float4*)&sm[SM_XP + k * 68 + ty * 4];
                float4 av = *(float4*)&sm[SM_AP + k * 68 + ty * 4];
                unsigned long long wsp0, wsp1, wnp0, wnp1;
                {
                    float4 ws = *(float4*)&sm[SM_W + (kp * 16 + k) * 64 + tx * 4];
                    float4 wn = *(float4*)&sm[SM_W + (64 + kp * 16 + k) * 64 + tx * 4];
                    wsp0 = pack2(ws.x, ws.y); wsp1 = pack2(ws.z, ws.w);
                    wnp0 = pack2(wn.x, wn.y); wnp1 = pack2(wn.z, wn.w);
                }
                unsigned long long xs[4], as_[4];
                xs[0] = pack2(xv.x, xv.x); xs[1] = pack2(xv.y, xv.y);
                xs[2] = pack2(xv.z, xv.z); xs[3] = pack2(xv.w, xv.w);
                as_[0] = pack2(av.x, av.x); as_[1] = pack2(av.y, av.y);
                as_[2] = pack2(av.z, av.z); as_[3] = pack2(av.w, av.w);
#pragma unroll
                for (int i = 0; i < 4; i++) {
                    acc[i][0] = fma2(wsp0, xs[i], acc[i][0]);
                    acc[i][0] = fma2(wnp0, as_[i], acc[i][0]);
                    acc[i][1] = fma2(wsp1, xs[i], acc[i][1]);
                    acc[i][1] = fma2(wnp1, as_[i], acc[i][1]);
                }
            }
        }
        // relu + bias -> sH
#pragma unroll
        for (int i = 0; i < 4; i++) {
            float h0, h1, h2, h3;
            unpack2(acc[i][0], h0, h1);
            unpack2(acc[i][1], h2, h3);
            float4 hv;
            hv.x = fmaxf(h0 + bb.x, 0.f);
            hv.y = fmaxf(h1 + bb.y, 0.f);
            hv.z = fmaxf(h2 + bb.z, 0.f);
            hv.w = fmaxf(h3 + bb.w, 0.f);
            *(float4*)&sm[SM_H + (ty * 4 + i) * 68 + tx * 4] = hv;
        }
        __syncthreads();
        // epilogue: p2h = fp16(h@Wn2); q2 = h@Ws2.
        {
            int n = tid >> 2, part = tid & 3;
            unsigned long long o[4] = {0ull, 0ull, 0ull, 0ull};
#pragma unroll 8
            for (int k = 0; k < 64; k++) {
                float hv = sm[SM_H + n * 68 + k];
                unsigned long long hs = pack2(hv, hv);
                float4 w0 = *(float4*)&sm[SM_W2 + k * 32 + part * 8];
                float4 w1 = *(float4*)&sm[SM_W2 + k * 32 + part * 8 + 4];
                o[0] = fma2(pack2(w0.x, w0.y), hs, o[0]);
                o[1] = fma2(pack2(w0.z, w0.w), hs, o[1]);
                o[2] = fma2(pack2(w1.x, w1.y), hs, o[2]);
                o[3] = fma2(pack2(w1.z, w1.w), hs, o[3]);
            }
            int node = node0 + n;
            if (node < N_NODES) {
                float f0, f1, f2, f3, f4, f5, f6, f7;
                unpack2(o[0], f0, f1); unpack2(o[1], f2, f3);
                unpack2(o[2], f4, f5); unpack2(o[3], f6, f7);
                if (part < 2) {
                    __half2 ha = __floats2half2_rn(f0, f1);
                    __half2 hb = __floats2half2_rn(f2, f3);
                    __half2 hc = __floats2half2_rn(f4, f5);
                    __half2 hd = __floats2half2_rn(f6, f7);
                    uint4 w;
                    w.x = *(unsigned int*)&ha;
                    w.y = *(unsigned int*)&hb;
                    w.z = *(unsigned int*)&hc;
                    w.w = *(unsigned int*)&hd;
                    *(uint4*)(g_p2h + (size_t)node * C + part * 8) = w;
                } else {
                    float4 r0 = make_float4(f0, f1, f2, f3);
                    float4 r1 = make_float4(f4, f5, f6, f7);
                    *(float4*)(g_q2 + (size_t)node * C + (part - 2) * 8)     = r0;
                    *(float4*)(g_q2 + (size_t)node * C + (part - 2) * 8 + 4) = r1;
                }
            }
        }
        __syncthreads();
    }
}

// ---------------- gather2 + output: out = q2 + mean_agg(p2h) + b2 -------
__global__ void gather2_out_kernel(const float* __restrict__ b2,
                                   float* __restrict__ out) {
    int node = blockIdx.x * 64 + (threadIdx.x >> 2);
    int l = threadIdx.x & 3;
    if (node >= N_NODES) return;
    int beg = g_off[node], end = g_off[node + 1];
    float4 acc = make_float4(0.f, 0.f, 0.f, 0.f);
    int i = beg;
    for (; i + 4 <= end; i += 4) {
        uint2 w0 = *(const uint2*)(g_p2h + (size_t)g_csr_src[i]     * C + l * 4);
        uint2 w1 = *(const uint2*)(g_p2h + (size_t)g_csr_src[i + 1] * C + l * 4);
        uint2 w2 = *(const uint2*)(g_p2h + (size_t)g_csr_src[i + 2] * C + l * 4);
        uint2 w3 = *(const uint2*)(g_p2h + (size_t)g_csr_src[i + 3] * C + l * 4);
#pragma unroll
        for (int u = 0; u < 4; u++) {
            uint2 w = (u == 0) ? w0 : (u == 1) ? w1 : (u == 2) ? w2 : w3;
            float2 f0 = __half22float2(*(__half2*)&w.x);
            float2 f1 = __half22float2(*(__half2*)&w.y);
            acc.x += f0.x; acc.y += f0.y; acc.z += f1.x; acc.w += f1.y;
        }
    }
    for (; i < end; i++) {
        uint2 w = *(const uint2*)(g_p2h + (size_t)g_csr_src[i] * C + l * 4);
        float2 f0 = __half22float2(*(__half2*)&w.x);
        float2 f1 = __half22float2(*(__half2*)&w.y);
        acc.x += f0.x; acc.y += f0.y; acc.z += f1.x; acc.w += f1.y;
    }
    float inv = 1.0f / (float)max(end - beg, 1);
    float4 q = *(const float4*)(g_q2 + (size_t)node * C + l * 4);
    float4 bv = *(const float4*)(b2 + l * 4);
    float4 r;
    r.x = q.x + acc.x * inv + bv.x;
    r.y = q.y + acc.y * inv + bv.y;
    r.z = q.z + acc.z * inv + bv.z;
    r.w = q.w + acc.w * inv + bv.w;
    *(float4*)(out + (size_t)node * C + l * 4) = r;
}

// ---------------- launch ----------------
extern "C" void kernel_launch(void* const* d_in, const int* in_sizes, int n_in,
                              void* d_out, int out_size) {
    const float* x   = (const float*)d_in[0];
    const int*   src = (const int*)d_in[1];
    const int*   dst = (const int*)d_in[2];
    const float* Ws1 = (const float*)d_in[3];
    const float* Wn1 = (const float*)d_in[4];
    const float* b1  = (const float*)d_in[5];
    const float* Ws2 = (const float*)d_in[6];
    const float* Wn2 = (const float*)d_in[7];
    const float* b2  = (const float*)d_in[8];
    float* out = (float*)d_out;

    // host-side attribute set; runs at capture time, not during replay
    cudaFuncSetAttribute(layer1_kernel,
                         cudaFuncAttributeMaxDynamicSharedMemorySize,
                         SM_TOT * (int)sizeof(float));

    detect_zero_kernel<<<(N_NODES + 255) / 256, 256>>>((const unsigned int*)src);
    convert_hist_kernel<<<(N_EDGES + 255) / 256, 256>>>(src, dst, x);
    scan_fused_kernel<<<1, 1024>>>();
    fill_kernel<<<(N_EDGES + 255) / 256, 256>>>();
    gather1_kernel<<<(N_NODES + 15) / 16, 256>>>();
    layer1_kernel<<<296, 256, SM_TOT * (int)sizeof(float)>>>(x, Ws1, Wn1, b1, Wn2, Ws2);
    gather2_out_kernel<<<(N_NODES + 63) / 64, 256>>>(b2, out);
}